// round 1
// baseline (speedup 1.0000x reference)
#include <cuda_runtime.h>
#include <math.h>

#define N_NODES   100000
#define N_EDGES   1600000
#define N_GRAPHS  256
#define IN_DIM    64
#define HID       128
#define RELU_COEF 0.05f

// ---------------- scratch (no allocation allowed) ----------------
__device__ float g_agg1[(size_t)N_NODES * IN_DIM];   // 25.6 MB
__device__ float g_agg2[(size_t)N_NODES * HID];      // 51.2 MB
__device__ float g_h1  [(size_t)N_NODES * HID];      // 51.2 MB
__device__ float g_h2  [(size_t)N_NODES * HID];      // 51.2 MB
__device__ float g_pool[N_GRAPHS * HID];

__device__ __forceinline__ float lrelu(float v) {
    return v > 0.f ? v : RELU_COEF * v;
}

// ---------------- zero fill ----------------
__global__ void zero_kernel(float4* p, int n4) {
    int i = blockIdx.x * blockDim.x + threadIdx.x;
    if (i < n4) p[i] = make_float4(0.f, 0.f, 0.f, 0.f);
}

// ---------------- edge scatter: agg[dst] += x[src] * w ----------------
// one thread handles one float4 of one edge's feature vector
template<int D>
__global__ void scatter_kernel(const float* __restrict__ x,
                               const int*   __restrict__ src,
                               const int*   __restrict__ dst,
                               const float* __restrict__ w,
                               float*       __restrict__ agg)
{
    constexpr int V = D / 4;          // float4 slots per edge
    int t = blockIdx.x * blockDim.x + threadIdx.x;
    int total = N_EDGES * V;
    if (t >= total) return;
    int e = t / V;                    // V is power of 2 -> shift
    int f = (t - e * V) * 4;
    int s = src[e];
    int d = dst[e];
    float ww = w[e];
    float4 v = *(const float4*)(x + (size_t)s * D + f);
    float* o = agg + (size_t)d * D + f;
    atomicAdd(o + 0, v.x * ww);
    atomicAdd(o + 1, v.y * ww);
    atomicAdd(o + 2, v.z * ww);
    atomicAdd(o + 3, v.w * ww);
}

// ---------------- fused dual-input linear + leaky ----------------
// out[n] = lrelu( A1[n] @ W1 + A2[n] @ W2 + bias )   (128 outputs)
// tile: 64 nodes x 128 outs, 256 threads, each thread: 8 nodes x 4 outs
template<int K1, int K2>
__global__ void __launch_bounds__(256)
linear2_kernel(const float* __restrict__ A1, const float* __restrict__ A2,
               const float* __restrict__ W1, const float* __restrict__ W2,
               const float* __restrict__ bias, float* __restrict__ out)
{
    constexpr int K  = K1 + K2;
    constexpr int KC = 32;
    __shared__ float As[64][KC];      // 8 KB
    __shared__ float Ws[KC][128];     // 16 KB
    const int n0  = blockIdx.x * 64;
    const int tid = threadIdx.x;
    const int tj  = tid & 31;         // out column group: j = tj*4
    const int tn  = tid >> 5;         // node group: nodes n0 + tn*8 .. +7

    float acc[8][4];
#pragma unroll
    for (int i = 0; i < 8; i++)
#pragma unroll
        for (int j = 0; j < 4; j++) acc[i][j] = 0.f;

    for (int kc = 0; kc < K; kc += KC) {
        // load A chunk: 64 x 32 floats = 512 float4, 2 per thread
#pragma unroll
        for (int r = 0; r < 2; r++) {
            int i  = tid + r * 256;
            int n  = i >> 3;
            int k4 = (i & 7) << 2;
            int gn = n0 + n, gk = kc + k4;
            float4 v = make_float4(0.f, 0.f, 0.f, 0.f);
            if (gn < N_NODES) {
                const float* p = (gk < K1) ? (A1 + (size_t)gn * K1 + gk)
                                           : (A2 + (size_t)gn * K2 + (gk - K1));
                v = *(const float4*)p;
            }
            *(float4*)&As[n][k4] = v;
        }
        // load W chunk: 32 x 128 floats = 1024 float4, 4 per thread
#pragma unroll
        for (int r = 0; r < 4; r++) {
            int i  = tid + r * 256;
            int k  = i >> 5;
            int j4 = (i & 31) << 2;
            int gk = kc + k;
            const float* p = (gk < K1) ? (W1 + (size_t)gk * 128 + j4)
                                       : (W2 + (size_t)(gk - K1) * 128 + j4);
            *(float4*)&Ws[k][j4] = *(const float4*)p;
        }
        __syncthreads();
#pragma unroll
        for (int k = 0; k < KC; k++) {
            float4 wv = *(const float4*)&Ws[k][tj << 2];
#pragma unroll
            for (int nn = 0; nn < 8; nn++) {
                float a = As[(tn << 3) + nn][k];
                acc[nn][0] += a * wv.x;
                acc[nn][1] += a * wv.y;
                acc[nn][2] += a * wv.z;
                acc[nn][3] += a * wv.w;
            }
        }
        __syncthreads();
    }
    float4 bv = *(const float4*)(bias + (tj << 2));
#pragma unroll
    for (int nn = 0; nn < 8; nn++) {
        int n = n0 + (tn << 3) + nn;
        if (n < N_NODES) {
            float4 r;
            r.x = lrelu(acc[nn][0] + bv.x);
            r.y = lrelu(acc[nn][1] + bv.y);
            r.z = lrelu(acc[nn][2] + bv.z);
            r.w = lrelu(acc[nn][3] + bv.w);
            *(float4*)(out + (size_t)n * 128 + (tj << 2)) = r;
        }
    }
}

// ---------------- fused gate + graph pooling ----------------
// hcat = [h2 (128), x0 (64)]; sx = clip(hcat@Wsig+bsig, +-30)
// g = 1/(1+exp(sx)) * tanh(hcat@Wtanh+btanh); pool[batch[n]] += g
__global__ void __launch_bounds__(256)
gate_pool_kernel(const float* __restrict__ h2, const float* __restrict__ x0,
                 const float* __restrict__ Wsig, const float* __restrict__ Wtanh,
                 const float* __restrict__ bsig, const float* __restrict__ btanh,
                 const int*   __restrict__ batch, float* __restrict__ pool)
{
    constexpr int K1 = HID;     // h2 part
    constexpr int K2 = IN_DIM;  // x part
    constexpr int K  = K1 + K2; // 192
    constexpr int KC = 32;
    __shared__ float As [64][KC];   // 8 KB
    __shared__ float WsS[KC][128];  // 16 KB
    __shared__ float WsT[KC][128];  // 16 KB
    const int n0  = blockIdx.x * 64;
    const int tid = threadIdx.x;
    const int tj  = tid & 31;
    const int tn  = tid >> 5;

    float accS[8][4], accT[8][4];
#pragma unroll
    for (int i = 0; i < 8; i++)
#pragma unroll
        for (int j = 0; j < 4; j++) { accS[i][j] = 0.f; accT[i][j] = 0.f; }

    for (int kc = 0; kc < K; kc += KC) {
#pragma unroll
        for (int r = 0; r < 2; r++) {
            int i  = tid + r * 256;
            int n  = i >> 3;
            int k4 = (i & 7) << 2;
            int gn = n0 + n, gk = kc + k4;
            float4 v = make_float4(0.f, 0.f, 0.f, 0.f);
            if (gn < N_NODES) {
                const float* p = (gk < K1) ? (h2 + (size_t)gn * K1 + gk)
                                           : (x0 + (size_t)gn * K2 + (gk - K1));
                v = *(const float4*)p;
            }
            *(float4*)&As[n][k4] = v;
        }
#pragma unroll
        for (int r = 0; r < 4; r++) {
            int i  = tid + r * 256;
            int k  = i >> 5;
            int j4 = (i & 31) << 2;
            int gk = kc + k;
            *(float4*)&WsS[k][j4] = *(const float4*)(Wsig  + (size_t)gk * 128 + j4);
            *(float4*)&WsT[k][j4] = *(const float4*)(Wtanh + (size_t)gk * 128 + j4);
        }
        __syncthreads();
#pragma unroll
        for (int k = 0; k < KC; k++) {
            float4 ws = *(const float4*)&WsS[k][tj << 2];
            float4 wt = *(const float4*)&WsT[k][tj << 2];
#pragma unroll
            for (int nn = 0; nn < 8; nn++) {
                float a = As[(tn << 3) + nn][k];
                accS[nn][0] += a * ws.x; accS[nn][1] += a * ws.y;
                accS[nn][2] += a * ws.z; accS[nn][3] += a * ws.w;
                accT[nn][0] += a * wt.x; accT[nn][1] += a * wt.y;
                accT[nn][2] += a * wt.z; accT[nn][3] += a * wt.w;
            }
        }
        __syncthreads();
    }

    float4 bs = *(const float4*)(bsig  + (tj << 2));
    float4 bt = *(const float4*)(btanh + (tj << 2));

    // run-length compress consecutive nodes with the same batch id (batch sorted)
    int curb = -1;
    float s0 = 0.f, s1 = 0.f, s2 = 0.f, s3 = 0.f;
#pragma unroll
    for (int nn = 0; nn < 8; nn++) {
        int n = n0 + (tn << 3) + nn;
        if (n >= N_NODES) break;
        int b = batch[n];
        float sx0 = fminf(fmaxf(accS[nn][0] + bs.x, -30.f), 30.f);
        float sx1 = fminf(fmaxf(accS[nn][1] + bs.y, -30.f), 30.f);
        float sx2 = fminf(fmaxf(accS[nn][2] + bs.z, -30.f), 30.f);
        float sx3 = fminf(fmaxf(accS[nn][3] + bs.w, -30.f), 30.f);
        float v0 = tanhf(accT[nn][0] + bt.x) / (1.f + expf(sx0));
        float v1 = tanhf(accT[nn][1] + bt.y) / (1.f + expf(sx1));
        float v2 = tanhf(accT[nn][2] + bt.z) / (1.f + expf(sx2));
        float v3 = tanhf(accT[nn][3] + bt.w) / (1.f + expf(sx3));
        if (b != curb) {
            if (curb >= 0) {
                float* pp = pool + (size_t)curb * 128 + (tj << 2);
                atomicAdd(pp + 0, s0); atomicAdd(pp + 1, s1);
                atomicAdd(pp + 2, s2); atomicAdd(pp + 3, s3);
            }
            curb = b; s0 = v0; s1 = v1; s2 = v2; s3 = v3;
        } else {
            s0 += v0; s1 += v1; s2 += v2; s3 += v3;
        }
    }
    if (curb >= 0) {
        float* pp = pool + (size_t)curb * 128 + (tj << 2);
        atomicAdd(pp + 0, s0); atomicAdd(pp + 1, s1);
        atomicAdd(pp + 2, s2); atomicAdd(pp + 3, s3);
    }
}

// ---------------- head MLP: one block per graph ----------------
__global__ void __launch_bounds__(256)
head_kernel(const float* __restrict__ pool,
            const float* __restrict__ Wf1, const float* __restrict__ bf1,
            const float* __restrict__ Wf2, const float* __restrict__ bf2,
            const float* __restrict__ Wout, const float* __restrict__ bout,
            float* __restrict__ out)
{
    __shared__ float p[128], f1[128], f2[258], red[256];
    const int g = blockIdx.x, tid = threadIdx.x;
    if (tid < 128) p[tid] = pool[(size_t)g * 128 + tid];
    __syncthreads();
    if (tid < 128) {
        float s = bf1[tid];
#pragma unroll 8
        for (int k = 0; k < 128; k++) s += p[k] * Wf1[k * 128 + tid];
        f1[tid] = lrelu(s);
    }
    __syncthreads();
    for (int j = tid; j < 258; j += 256) {
        float s = bf2[j];
#pragma unroll 8
        for (int k = 0; k < 128; k++) s += f1[k] * Wf2[k * 258 + j];
        f2[j] = lrelu(s);
    }
    __syncthreads();
    float s = 0.f;
    for (int k = tid; k < 258; k += 256) s += f2[k] * Wout[k];
    red[tid] = s;
    __syncthreads();
    for (int off = 128; off > 0; off >>= 1) {
        if (tid < off) red[tid] += red[tid + off];
        __syncthreads();
    }
    if (tid == 0) {
        float v = red[0] + bout[0];
        out[g] = 1.f / (1.f + expf(-v));
    }
}

// ---------------- launch ----------------
extern "C" void kernel_launch(void* const* d_in, const int* in_sizes, int n_in,
                              void* d_out, int out_size)
{
    const float* x      = (const float*)d_in[0];
    const int*   ei     = (const int*)  d_in[1];
    const int*   batch  = (const int*)  d_in[2];
    const float* eattr  = (const float*)d_in[3];
    const float* Wrel1  = (const float*)d_in[4];
    const float* brel1  = (const float*)d_in[5];
    const float* Wroot1 = (const float*)d_in[6];
    const float* Wrel2  = (const float*)d_in[7];
    const float* brel2  = (const float*)d_in[8];
    const float* Wroot2 = (const float*)d_in[9];
    const float* Wsig   = (const float*)d_in[10];
    const float* bsig   = (const float*)d_in[11];
    const float* Wtanh  = (const float*)d_in[12];
    const float* btanh  = (const float*)d_in[13];
    const float* Wf1    = (const float*)d_in[14];
    const float* bf1    = (const float*)d_in[15];
    const float* Wf2    = (const float*)d_in[16];
    const float* bf2    = (const float*)d_in[17];
    const float* Wout   = (const float*)d_in[18];
    const float* bout   = (const float*)d_in[19];
    float* out = (float*)d_out;

    const int* src = ei;
    const int* dst = ei + N_EDGES;

    float *agg1, *agg2, *h1, *h2, *pool;
    cudaGetSymbolAddress((void**)&agg1, g_agg1);
    cudaGetSymbolAddress((void**)&agg2, g_agg2);
    cudaGetSymbolAddress((void**)&h1,   g_h1);
    cudaGetSymbolAddress((void**)&h2,   g_h2);
    cudaGetSymbolAddress((void**)&pool, g_pool);

    const int nodeBlocks = (N_NODES + 63) / 64;

    // ---- layer 1 ----
    {
        int n4 = N_NODES * IN_DIM / 4;
        zero_kernel<<<(n4 + 255) / 256, 256>>>((float4*)agg1, n4);
        int total = N_EDGES * (IN_DIM / 4);
        scatter_kernel<IN_DIM><<<(total + 255) / 256, 256>>>(x, src, dst, eattr, agg1);
        linear2_kernel<IN_DIM, IN_DIM><<<nodeBlocks, 256>>>(agg1, x, Wrel1, Wroot1, brel1, h1);
    }
    // ---- layer 2 ----
    {
        int n4 = N_NODES * HID / 4;
        zero_kernel<<<(n4 + 255) / 256, 256>>>((float4*)agg2, n4);
        int total = N_EDGES * (HID / 4);
        scatter_kernel<HID><<<(total + 255) / 256, 256>>>(h1, src, dst, eattr, agg2);
        linear2_kernel<HID, HID><<<nodeBlocks, 256>>>(agg2, h1, Wrel2, Wroot2, brel2, h2);
    }
    // ---- gate + pool ----
    {
        int n4 = N_GRAPHS * HID / 4;
        zero_kernel<<<(n4 + 255) / 256, 256>>>((float4*)pool, n4);
        gate_pool_kernel<<<nodeBlocks, 256>>>(h2, x, Wsig, Wtanh, bsig, btanh, batch, pool);
    }
    // ---- head ----
    head_kernel<<<N_GRAPHS, 256>>>(pool, Wf1, bf1, Wf2, bf2, Wout, bout, out);
}

// round 2
// speedup vs baseline: 1.8436x; 1.8436x over previous
#include <cuda_runtime.h>
#include <math.h>

#define N_NODES   100000
#define N_EDGES   1600000
#define N_GRAPHS  256
#define IN_DIM    64
#define HID       128
#define RELU_COEF 0.05f

typedef unsigned long long ull;

// ---------------- scratch (no allocation allowed) ----------------
__device__ float g_agg1[(size_t)N_NODES * IN_DIM];
__device__ float g_agg2[(size_t)N_NODES * HID];
__device__ float g_h1  [(size_t)N_NODES * HID];
__device__ float g_h2  [(size_t)N_NODES * HID];
__device__ float g_pool[N_GRAPHS * HID];
__device__ int   g_deg   [N_NODES];
__device__ int   g_rowptr[N_NODES];
__device__ int   g_fill  [N_NODES];
__device__ int2  g_epak  [N_EDGES];     // (src, bits(w)) sorted by dst
__device__ int   g_blksum[512];

__device__ __forceinline__ float lrelu(float v) {
    return v > 0.f ? v : RELU_COEF * v;
}

// packed f32x2 helpers (sm_100+): 2 fp32 FMAs per issue, bit-exact fp32
#define FMA2(acc, a, b) asm("fma.rn.f32x2 %0, %1, %2, %0;" : "+l"(acc) : "l"(a), "l"(b))
#define PACK2(d, x)     asm("mov.b64 %0, {%1, %1};" : "=l"(d) : "f"(x))
#define UNPACK2(lo, hi, v) asm("mov.b64 {%0, %1}, %2;" : "=f"(lo), "=f"(hi) : "l"(v))

// ---------------- small utility kernels ----------------
__global__ void zero_f4_kernel(float4* p, int n4) {
    int i = blockIdx.x * blockDim.x + threadIdx.x;
    if (i < n4) p[i] = make_float4(0.f, 0.f, 0.f, 0.f);
}
__global__ void zero_int_kernel(int* p, int n) {
    int i = blockIdx.x * blockDim.x + threadIdx.x;
    if (i < n) p[i] = 0;
}

// ---------------- CSR build: histogram / scan / fill ----------------
__global__ void hist_kernel(const int* __restrict__ dst, int* __restrict__ deg) {
    int e = blockIdx.x * blockDim.x + threadIdx.x;
    if (e < N_EDGES) atomicAdd(&deg[dst[e]], 1);
}
__global__ void scan1_kernel(const int* __restrict__ deg, int* __restrict__ rowptr,
                             int* __restrict__ blksum) {
    __shared__ int s[256];
    int i = blockIdx.x * 256 + threadIdx.x;
    int v = (i < N_NODES) ? deg[i] : 0;
    s[threadIdx.x] = v;
    __syncthreads();
    for (int off = 1; off < 256; off <<= 1) {
        int t = 0;
        if (threadIdx.x >= off) t = s[threadIdx.x - off];
        __syncthreads();
        s[threadIdx.x] += t;
        __syncthreads();
    }
    if (i < N_NODES) rowptr[i] = s[threadIdx.x] - v;    // exclusive
    if (threadIdx.x == 255) blksum[blockIdx.x] = s[255];
}
__global__ void scan2_kernel(int* blksum, int nblk) {
    int run = 0;
    for (int b = 0; b < nblk; b++) { int t = blksum[b]; blksum[b] = run; run += t; }
}
__global__ void scan3_kernel(int* __restrict__ rowptr, int* __restrict__ fill,
                             const int* __restrict__ blksum) {
    int i = blockIdx.x * 256 + threadIdx.x;
    if (i < N_NODES) {
        int r = rowptr[i] + blksum[blockIdx.x];
        rowptr[i] = r;
        fill[i] = r;
    }
}
__global__ void fill_kernel(const int* __restrict__ src, const int* __restrict__ dst,
                            const float* __restrict__ w, int* __restrict__ fill,
                            int2* __restrict__ epak) {
    int e = blockIdx.x * blockDim.x + threadIdx.x;
    if (e < N_EDGES) {
        int pos = atomicAdd(&fill[dst[e]], 1);
        epak[pos] = make_int2(src[e], __float_as_int(w[e]));
    }
}

// ---------------- gather aggregation: warp per node ----------------
template<int D>
__global__ void __launch_bounds__(256)
gather_kernel(const float* __restrict__ x, const int* __restrict__ rowptr,
              const int* __restrict__ deg, const int2* __restrict__ epak,
              float* __restrict__ agg)
{
    int warp = (blockIdx.x * blockDim.x + threadIdx.x) >> 5;
    int lane = threadIdx.x & 31;
    if (warp >= N_NODES) return;
    int start = rowptr[warp];
    int d = deg[warp];
    if (D == 128) {
        float4 acc = make_float4(0.f, 0.f, 0.f, 0.f);
        for (int i = 0; i < d; i++) {
            int2 p = epak[start + i];
            float ww = __int_as_float(p.y);
            float4 v = *(const float4*)(x + (size_t)p.x * 128 + lane * 4);
            acc.x += ww * v.x; acc.y += ww * v.y;
            acc.z += ww * v.z; acc.w += ww * v.w;
        }
        *(float4*)(agg + (size_t)warp * 128 + lane * 4) = acc;
    } else {
        float2 acc = make_float2(0.f, 0.f);
        for (int i = 0; i < d; i++) {
            int2 p = epak[start + i];
            float ww = __int_as_float(p.y);
            float2 v = *(const float2*)(x + (size_t)p.x * 64 + lane * 2);
            acc.x += ww * v.x; acc.y += ww * v.y;
        }
        *(float2*)(agg + (size_t)warp * 64 + lane * 2) = acc;
    }
}

// ---------------- fused dual-input linear + leaky (f32x2 packed) -----------
// out[n] = lrelu( A1[n]@W1 + A2[n]@W2 + bias )  (128 outputs)
// 64 nodes x 128 cols per block; 256 threads; thread = 4 node-pairs x 4 cols
template<int K1, int K2>
__global__ void __launch_bounds__(256)
linear2_kernel(const float* __restrict__ A1, const float* __restrict__ A2,
               const float* __restrict__ W1, const float* __restrict__ W2,
               const float* __restrict__ bias, float* __restrict__ out)
{
    constexpr int K  = K1 + K2;
    constexpr int KC = 32;
    __shared__ float Ast[KC][64];     // transposed A tile: 8 KB
    __shared__ float Ws[KC][128];     // 16 KB
    const int n0  = blockIdx.x * 64;
    const int tid = threadIdx.x;
    const int tj  = tid & 31;         // col group: cols tj*4..+3
    const int tn  = tid >> 5;         // node group: nodes n0 + tn*8..+7

    ull acc[4][4];
#pragma unroll
    for (int p = 0; p < 4; p++)
#pragma unroll
        for (int c = 0; c < 4; c++) acc[p][c] = 0ULL;

    for (int kc = 0; kc < K; kc += KC) {
        // A tile: 64x32 floats, transposed into Ast[k][n]
#pragma unroll
        for (int r = 0; r < 2; r++) {
            int i  = tid + r * 256;
            int n  = i >> 3;
            int k4 = (i & 7) << 2;
            int gn = n0 + n, gk = kc + k4;
            float4 v = make_float4(0.f, 0.f, 0.f, 0.f);
            if (gn < N_NODES) {
                const float* p = (gk < K1) ? (A1 + (size_t)gn * K1 + gk)
                                           : (A2 + (size_t)gn * K2 + (gk - K1));
                v = *(const float4*)p;
            }
            Ast[k4 + 0][n] = v.x; Ast[k4 + 1][n] = v.y;
            Ast[k4 + 2][n] = v.z; Ast[k4 + 3][n] = v.w;
        }
        // W tile: 32x128
#pragma unroll
        for (int r = 0; r < 4; r++) {
            int i  = tid + r * 256;
            int k  = i >> 5;
            int j4 = (i & 31) << 2;
            int gk = kc + k;
            const float* p = (gk < K1) ? (W1 + (size_t)gk * 128 + j4)
                                       : (W2 + (size_t)(gk - K1) * 128 + j4);
            *(float4*)&Ws[k][j4] = *(const float4*)p;
        }
        __syncthreads();
#pragma unroll 8
        for (int k = 0; k < KC; k++) {
            float4 w4 = *(const float4*)&Ws[k][tj << 2];
            ull wd0, wd1, wd2, wd3;
            PACK2(wd0, w4.x); PACK2(wd1, w4.y); PACK2(wd2, w4.z); PACK2(wd3, w4.w);
            const ull* ap = (const ull*)&Ast[k][tn << 3];
            ull a0 = ap[0], a1 = ap[1], a2 = ap[2], a3 = ap[3];
            FMA2(acc[0][0], a0, wd0); FMA2(acc[0][1], a0, wd1);
            FMA2(acc[0][2], a0, wd2); FMA2(acc[0][3], a0, wd3);
            FMA2(acc[1][0], a1, wd0); FMA2(acc[1][1], a1, wd1);
            FMA2(acc[1][2], a1, wd2); FMA2(acc[1][3], a1, wd3);
            FMA2(acc[2][0], a2, wd0); FMA2(acc[2][1], a2, wd1);
            FMA2(acc[2][2], a2, wd2); FMA2(acc[2][3], a2, wd3);
            FMA2(acc[3][0], a3, wd0); FMA2(acc[3][1], a3, wd1);
            FMA2(acc[3][2], a3, wd2); FMA2(acc[3][3], a3, wd3);
        }
        __syncthreads();
    }
    float4 bv = *(const float4*)(bias + (tj << 2));
#pragma unroll
    for (int p = 0; p < 4; p++) {
        float lo[4], hi[4];
#pragma unroll
        for (int c = 0; c < 4; c++) UNPACK2(lo[c], hi[c], acc[p][c]);
        int nA = n0 + (tn << 3) + 2 * p;
        if (nA < N_NODES) {
            float4 r;
            r.x = lrelu(lo[0] + bv.x); r.y = lrelu(lo[1] + bv.y);
            r.z = lrelu(lo[2] + bv.z); r.w = lrelu(lo[3] + bv.w);
            *(float4*)(out + (size_t)nA * 128 + (tj << 2)) = r;
        }
        if (nA + 1 < N_NODES) {
            float4 r;
            r.x = lrelu(hi[0] + bv.x); r.y = lrelu(hi[1] + bv.y);
            r.z = lrelu(hi[2] + bv.z); r.w = lrelu(hi[3] + bv.w);
            *(float4*)(out + (size_t)(nA + 1) * 128 + (tj << 2)) = r;
        }
    }
}

// ---------------- fused gate + graph pooling (f32x2 packed) ----------------
__global__ void __launch_bounds__(256)
gate_pool_kernel(const float* __restrict__ h2, const float* __restrict__ x0,
                 const float* __restrict__ Wsig, const float* __restrict__ Wtanh,
                 const float* __restrict__ bsig, const float* __restrict__ btanh,
                 const int*   __restrict__ batch, float* __restrict__ pool)
{
    constexpr int K1 = HID;
    constexpr int K2 = IN_DIM;
    constexpr int K  = K1 + K2;   // 192
    constexpr int KC = 32;
    __shared__ float Ast[KC][64];   // 8 KB
    __shared__ float WsS[KC][128];  // 16 KB
    __shared__ float WsT[KC][128];  // 16 KB
    const int n0  = blockIdx.x * 64;
    const int tid = threadIdx.x;
    const int tj  = tid & 31;
    const int tn  = tid >> 5;

    ull accS[4][4], accT[4][4];
#pragma unroll
    for (int p = 0; p < 4; p++)
#pragma unroll
        for (int c = 0; c < 4; c++) { accS[p][c] = 0ULL; accT[p][c] = 0ULL; }

    for (int kc = 0; kc < K; kc += KC) {
#pragma unroll
        for (int r = 0; r < 2; r++) {
            int i  = tid + r * 256;
            int n  = i >> 3;
            int k4 = (i & 7) << 2;
            int gn = n0 + n, gk = kc + k4;
            float4 v = make_float4(0.f, 0.f, 0.f, 0.f);
            if (gn < N_NODES) {
                const float* p = (gk < K1) ? (h2 + (size_t)gn * K1 + gk)
                                           : (x0 + (size_t)gn * K2 + (gk - K1));
                v = *(const float4*)p;
            }
            Ast[k4 + 0][n] = v.x; Ast[k4 + 1][n] = v.y;
            Ast[k4 + 2][n] = v.z; Ast[k4 + 3][n] = v.w;
        }
#pragma unroll
        for (int r = 0; r < 4; r++) {
            int i  = tid + r * 256;
            int k  = i >> 5;
            int j4 = (i & 31) << 2;
            int gk = kc + k;
            *(float4*)&WsS[k][j4] = *(const float4*)(Wsig  + (size_t)gk * 128 + j4);
            *(float4*)&WsT[k][j4] = *(const float4*)(Wtanh + (size_t)gk * 128 + j4);
        }
        __syncthreads();
#pragma unroll 4
        for (int k = 0; k < KC; k++) {
            const ull* ap = (const ull*)&Ast[k][tn << 3];
            ull a0 = ap[0], a1 = ap[1], a2 = ap[2], a3 = ap[3];
            {
                float4 w4 = *(const float4*)&WsS[k][tj << 2];
                ull w0, w1, w2, w3;
                PACK2(w0, w4.x); PACK2(w1, w4.y); PACK2(w2, w4.z); PACK2(w3, w4.w);
                FMA2(accS[0][0], a0, w0); FMA2(accS[0][1], a0, w1);
                FMA2(accS[0][2], a0, w2); FMA2(accS[0][3], a0, w3);
                FMA2(accS[1][0], a1, w0); FMA2(accS[1][1], a1, w1);
                FMA2(accS[1][2], a1, w2); FMA2(accS[1][3], a1, w3);
                FMA2(accS[2][0], a2, w0); FMA2(accS[2][1], a2, w1);
                FMA2(accS[2][2], a2, w2); FMA2(accS[2][3], a2, w3);
                FMA2(accS[3][0], a3, w0); FMA2(accS[3][1], a3, w1);
                FMA2(accS[3][2], a3, w2); FMA2(accS[3][3], a3, w3);
            }
            {
                float4 w4 = *(const float4*)&WsT[k][tj << 2];
                ull w0, w1, w2, w3;
                PACK2(w0, w4.x); PACK2(w1, w4.y); PACK2(w2, w4.z); PACK2(w3, w4.w);
                FMA2(accT[0][0], a0, w0); FMA2(accT[0][1], a0, w1);
                FMA2(accT[0][2], a0, w2); FMA2(accT[0][3], a0, w3);
                FMA2(accT[1][0], a1, w0); FMA2(accT[1][1], a1, w1);
                FMA2(accT[1][2], a1, w2); FMA2(accT[1][3], a1, w3);
                FMA2(accT[2][0], a2, w0); FMA2(accT[2][1], a2, w1);
                FMA2(accT[2][2], a2, w2); FMA2(accT[2][3], a2, w3);
                FMA2(accT[3][0], a3, w0); FMA2(accT[3][1], a3, w1);
                FMA2(accT[3][2], a3, w2); FMA2(accT[3][3], a3, w3);
            }
        }
        __syncthreads();
    }

    float4 bs = *(const float4*)(bsig  + (tj << 2));
    float4 bt = *(const float4*)(btanh + (tj << 2));

    // unpack to per-node values
    float vS[8][4], vT[8][4];
#pragma unroll
    for (int p = 0; p < 4; p++)
#pragma unroll
        for (int c = 0; c < 4; c++) {
            UNPACK2(vS[2 * p][c], vS[2 * p + 1][c], accS[p][c]);
            UNPACK2(vT[2 * p][c], vT[2 * p + 1][c], accT[p][c]);
        }

    const float bsa[4] = {bs.x, bs.y, bs.z, bs.w};
    const float bta[4] = {bt.x, bt.y, bt.z, bt.w};

    // run-length compress consecutive nodes with same batch id (batch sorted)
    int curb = -1;
    float s[4] = {0.f, 0.f, 0.f, 0.f};
#pragma unroll
    for (int nn = 0; nn < 8; nn++) {
        int n = n0 + (tn << 3) + nn;
        if (n >= N_NODES) break;
        int b = batch[n];
        float v[4];
#pragma unroll
        for (int c = 0; c < 4; c++) {
            float sx = fminf(fmaxf(vS[nn][c] + bsa[c], -30.f), 30.f);
            v[c] = tanhf(vT[nn][c] + bta[c]) / (1.f + expf(sx));
        }
        if (b != curb) {
            if (curb >= 0) {
                float* pp = pool + (size_t)curb * 128 + (tj << 2);
                atomicAdd(pp + 0, s[0]); atomicAdd(pp + 1, s[1]);
                atomicAdd(pp + 2, s[2]); atomicAdd(pp + 3, s[3]);
            }
            curb = b;
            s[0] = v[0]; s[1] = v[1]; s[2] = v[2]; s[3] = v[3];
        } else {
            s[0] += v[0]; s[1] += v[1]; s[2] += v[2]; s[3] += v[3];
        }
    }
    if (curb >= 0) {
        float* pp = pool + (size_t)curb * 128 + (tj << 2);
        atomicAdd(pp + 0, s[0]); atomicAdd(pp + 1, s[1]);
        atomicAdd(pp + 2, s[2]); atomicAdd(pp + 3, s[3]);
    }
}

// ---------------- head MLP: one block per graph ----------------
__global__ void __launch_bounds__(256)
head_kernel(const float* __restrict__ pool,
            const float* __restrict__ Wf1, const float* __restrict__ bf1,
            const float* __restrict__ Wf2, const float* __restrict__ bf2,
            const float* __restrict__ Wout, const float* __restrict__ bout,
            float* __restrict__ out)
{
    __shared__ float p[128], f1[128], f2[258], red[256];
    const int g = blockIdx.x, tid = threadIdx.x;
    if (tid < 128) p[tid] = pool[(size_t)g * 128 + tid];
    __syncthreads();
    if (tid < 128) {
        float s = bf1[tid];
#pragma unroll 8
        for (int k = 0; k < 128; k++) s += p[k] * Wf1[k * 128 + tid];
        f1[tid] = lrelu(s);
    }
    __syncthreads();
    for (int j = tid; j < 258; j += 256) {
        float s = bf2[j];
#pragma unroll 8
        for (int k = 0; k < 128; k++) s += f1[k] * Wf2[k * 258 + j];
        f2[j] = lrelu(s);
    }
    __syncthreads();
    float s = 0.f;
    for (int k = tid; k < 258; k += 256) s += f2[k] * Wout[k];
    red[tid] = s;
    __syncthreads();
    for (int off = 128; off > 0; off >>= 1) {
        if (tid < off) red[tid] += red[tid + off];
        __syncthreads();
    }
    if (tid == 0) {
        float v = red[0] + bout[0];
        out[g] = 1.f / (1.f + expf(-v));
    }
}

// ---------------- launch ----------------
extern "C" void kernel_launch(void* const* d_in, const int* in_sizes, int n_in,
                              void* d_out, int out_size)
{
    const float* x      = (const float*)d_in[0];
    const int*   ei     = (const int*)  d_in[1];
    const int*   batch  = (const int*)  d_in[2];
    const float* eattr  = (const float*)d_in[3];
    const float* Wrel1  = (const float*)d_in[4];
    const float* brel1  = (const float*)d_in[5];
    const float* Wroot1 = (const float*)d_in[6];
    const float* Wrel2  = (const float*)d_in[7];
    const float* brel2  = (const float*)d_in[8];
    const float* Wroot2 = (const float*)d_in[9];
    const float* Wsig   = (const float*)d_in[10];
    const float* bsig   = (const float*)d_in[11];
    const float* Wtanh  = (const float*)d_in[12];
    const float* btanh  = (const float*)d_in[13];
    const float* Wf1    = (const float*)d_in[14];
    const float* bf1    = (const float*)d_in[15];
    const float* Wf2    = (const float*)d_in[16];
    const float* bf2    = (const float*)d_in[17];
    const float* Wout   = (const float*)d_in[18];
    const float* bout   = (const float*)d_in[19];
    float* out = (float*)d_out;

    const int* src = ei;
    const int* dst = ei + N_EDGES;

    float *agg1, *agg2, *h1, *h2, *pool;
    int *deg, *rowptr, *fill, *blksum;
    int2 *epak;
    cudaGetSymbolAddress((void**)&agg1,   g_agg1);
    cudaGetSymbolAddress((void**)&agg2,   g_agg2);
    cudaGetSymbolAddress((void**)&h1,     g_h1);
    cudaGetSymbolAddress((void**)&h2,     g_h2);
    cudaGetSymbolAddress((void**)&pool,   g_pool);
    cudaGetSymbolAddress((void**)&deg,    g_deg);
    cudaGetSymbolAddress((void**)&rowptr, g_rowptr);
    cudaGetSymbolAddress((void**)&fill,   g_fill);
    cudaGetSymbolAddress((void**)&epak,   g_epak);
    cudaGetSymbolAddress((void**)&blksum, g_blksum);

    const int nodeBlocks = (N_NODES + 63) / 64;
    const int scanBlocks = (N_NODES + 255) / 256;   // 391
    const int edgeBlocks = (N_EDGES + 255) / 256;

    // ---- CSR build (shared by both layers) ----
    zero_int_kernel<<<scanBlocks, 256>>>(deg, N_NODES);
    hist_kernel<<<edgeBlocks, 256>>>(dst, deg);
    scan1_kernel<<<scanBlocks, 256>>>(deg, rowptr, blksum);
    scan2_kernel<<<1, 1>>>(blksum, scanBlocks);
    scan3_kernel<<<scanBlocks, 256>>>(rowptr, fill, blksum);
    fill_kernel<<<edgeBlocks, 256>>>(src, dst, eattr, fill, epak);

    // ---- layer 1 ----
    gather_kernel<IN_DIM><<<(N_NODES * 32 + 255) / 256, 256>>>(x, rowptr, deg, epak, agg1);
    linear2_kernel<IN_DIM, IN_DIM><<<nodeBlocks, 256>>>(agg1, x, Wrel1, Wroot1, brel1, h1);
    // ---- layer 2 ----
    gather_kernel<HID><<<(N_NODES * 32 + 255) / 256, 256>>>(h1, rowptr, deg, epak, agg2);
    linear2_kernel<HID, HID><<<nodeBlocks, 256>>>(agg2, h1, Wrel2, Wroot2, brel2, h2);
    // ---- gate + pool ----
    {
        int n4 = N_GRAPHS * HID / 4;
        zero_f4_kernel<<<(n4 + 255) / 256, 256>>>((float4*)pool, n4);
        gate_pool_kernel<<<nodeBlocks, 256>>>(h2, x, Wsig, Wtanh, bsig, btanh, batch, pool);
    }
    // ---- head ----
    head_kernel<<<N_GRAPHS, 256>>>(pool, Wf1, bf1, Wf2, bf2, Wout, bout, out);
}